// round 2
// baseline (speedup 1.0000x reference)
#include <cuda_runtime.h>
#include <cstdint>
#include <cstddef>

// Problem constants
//  x: [16, 32, 32, 8, 16]  (B,H,W,I,Din)  fp32
//  W: [5, 5, 16, 256]      (kh,kw,cin,co) fp32, co = o*16+d
//  b: [1, 1, 16, 16]       fp32
//  out: [16, 32, 32, 16, 16] (B,H,W,O,D)  fp32
//
// conv batch n = i*16 + b_img (I-major, per reference transpose),
// routing for output batch p consumes conv images n = p*8 + q, q=0..7
// (the reference's "faithful" reshape bug).

// 128 images * 32*32 * 256 ch = 33.5M floats (128 MB) vote scratch.
__device__ float g_votes[128 * 32 * 32 * 256];

__device__ __forceinline__ void cp_async16(void* smem, const void* gmem) {
    uint32_t s = (uint32_t)__cvta_generic_to_shared(smem);
    asm volatile("cp.async.cg.shared.global [%0], [%1], 16;\n" :: "r"(s), "l"(gmem));
}

// ---------------------------------------------------------------------------
// Conv kernel: block = (image n, row h). 256 threads.
// Thread tile: 8 w-positions x 4 consecutive co  -> 32 accumulators.
// K loop: 25 chunks of (kh,kw), each chunk = 16 cin x 256 co weights (16 KB)
// double-buffered in smem via cp.async.
// ---------------------------------------------------------------------------
__global__ __launch_bounds__(256) void conv_kernel(const float* __restrict__ x,
                                                   const float* __restrict__ Wt) {
    const int bid  = blockIdx.x;     // n*32 + h
    const int n    = bid >> 5;
    const int h    = bid & 31;
    const int icap = n >> 4;         // i = n / 16
    const int bimg = n & 15;         // b = n % 16
    const int t    = threadIdx.x;

    __shared__ float xs[5 * 36 * 16];     // rows h-2..h+2, w padded to [-2,34)
    __shared__ float ws[2][16 * 256];     // double-buffered weight chunk

    // ---- load x halo tile (zero padded) ----
    const float* xbase = x + (size_t)bimg * 131072 + icap * 16;
    for (int idx = t; idx < 720; idx += 256) {            // 720 float4 = 2880 floats
        int r   = idx / 144;
        int rem = idx - r * 144;
        int wp  = rem >> 2;                                // 0..35
        int c4  = (rem & 3) << 2;
        int hh  = h + r - 2;
        int w   = wp - 2;
        float4 v = make_float4(0.f, 0.f, 0.f, 0.f);
        if ((unsigned)hh < 32u && (unsigned)w < 32u)
            v = *(const float4*)(xbase + (size_t)hh * 4096 + w * 128 + c4);
        *(float4*)&xs[r * 576 + wp * 16 + c4] = v;
    }

    // ---- prefetch weight chunk 0 ----
    {
        const float4* wg = (const float4*)Wt;
        float4* wd = (float4*)ws[0];
        for (int j = t; j < 1024; j += 256) cp_async16(&wd[j], &wg[j]);
        asm volatile("cp.async.commit_group;\n");
    }

    const int co4   = (t & 63) << 2;     // 0..252 step 4
    const int wbase = (t >> 6) << 3;     // 0,8,16,24

    float acc[8][4];
#pragma unroll
    for (int a = 0; a < 8; ++a)
#pragma unroll
        for (int j = 0; j < 4; ++j) acc[a][j] = 0.f;

    int buf = 0;
    for (int k = 0; k < 25; ++k) {
        if (k + 1 < 25) {
            const float4* wg = (const float4*)(Wt + (size_t)(k + 1) * 4096);
            float4* wd = (float4*)ws[buf ^ 1];
            for (int j = t; j < 1024; j += 256) cp_async16(&wd[j], &wg[j]);
            asm volatile("cp.async.commit_group;\n");
            asm volatile("cp.async.wait_group 1;\n");   // chunk k has landed
        } else {
            asm volatile("cp.async.wait_group 0;\n");
        }
        __syncthreads();   // chunk k visible to all; prev compute done before overwrite

        const int kh = k / 5;
        const int kw = k - kh * 5;
        const float* xrow = &xs[kh * 576 + (wbase + kw) * 16];
        const float* wrow = ws[buf];
#pragma unroll
        for (int cin = 0; cin < 16; ++cin) {
            float4 wv = *(const float4*)&wrow[cin * 256 + co4];
#pragma unroll
            for (int a = 0; a < 8; ++a) {
                float xv = xrow[a * 16 + cin];
                acc[a][0] = fmaf(xv, wv.x, acc[a][0]);
                acc[a][1] = fmaf(xv, wv.y, acc[a][1]);
                acc[a][2] = fmaf(xv, wv.z, acc[a][2]);
                acc[a][3] = fmaf(xv, wv.w, acc[a][3]);
            }
        }
        __syncthreads();   // everyone done reading ws[buf] before next-next load
        buf ^= 1;
    }

    // ---- store votes [n, h, w, co] ----
    float* outp = g_votes + (size_t)((n * 32 + h) * 32) * 256;
#pragma unroll
    for (int a = 0; a < 8; ++a)
        *(float4*)&outp[(size_t)(wbase + a) * 256 + co4] = *(float4*)acc[a];
}

// ---------------------------------------------------------------------------
// Routing kernel: block = one output point (p, h, w). 256 threads = (o,d).
// 3 routing iterations fully fused in smem/registers.
// ---------------------------------------------------------------------------
__global__ __launch_bounds__(256) void routing_kernel(const float* __restrict__ bias,
                                                      float* __restrict__ out) {
    const int pix = blockIdx.x;            // p*1024 + h*32 + w
    const int t   = threadIdx.x;           // o*16 + d
    const int p   = pix >> 10;
    const int hw  = pix & 1023;

    __shared__ float v_s[8 * 256];         // votes [i][o*16+d]
    __shared__ float route_s[128];         // [i][o]
    __shared__ float logit_s[128];         // [i][o]
    __shared__ float act_s[256];           // [o*16+d]

    // load votes for conv images n = p*8 + q
    const float4* gb  = (const float4*)(g_votes + ((size_t)(p * 8) * 1024 + hw) * 256);
    float4* vs4 = (float4*)v_s;
#pragma unroll
    for (int j = 0; j < 2; ++j) {
        int idx = t + j * 256;             // 0..511
        int q = idx >> 6, c = idx & 63;
        vs4[idx] = gb[(size_t)q * 65536 + c];   // stride per q = 1024*256 floats
    }
    if (t < 128) logit_s[t] = 0.f;
    const float bval = bias[t];
    __syncthreads();

    const int o = t >> 4;                  // output capsule
    float act = 0.f;

#pragma unroll
    for (int it = 0; it < 3; ++it) {
        // softmax over o, per input capsule i. threads 0..127: i = t>>4, oo = t&15
        if (t < 128) {
            float l = logit_s[t];
            float m = l;
#pragma unroll
            for (int s = 8; s; s >>= 1)
                m = fmaxf(m, __shfl_xor_sync(0xffffffffu, m, s, 16));
            float e = __expf(l - m);
            float sum = e;
#pragma unroll
            for (int s = 8; s; s >>= 1)
                sum += __shfl_xor_sync(0xffffffffu, sum, s, 16);
            route_s[t] = e / sum;
        }
        __syncthreads();

        // preact[o][d] = sum_i route[i][o] * votes[i][o][d] + bias[o][d]
        float pre = bval;
#pragma unroll
        for (int q = 0; q < 8; ++q)
            pre = fmaf(route_s[q * 16 + o], v_s[q * 256 + t], pre);

        // squash: n2 over d (d = t&15 -> consecutive lanes, width-16 reduce)
        float sq = pre * pre;
#pragma unroll
        for (int s = 8; s; s >>= 1)
            sq += __shfl_xor_sync(0xffffffffu, sq, s, 16);
        act = pre * sqrtf(sq) / (1.f + sq);

        if (it < 2) {
            act_s[t] = act;
            __syncthreads();
            if (t < 128) {
                const int i = t >> 4, oo = t & 15;
                float ag = 0.f;
#pragma unroll
                for (int dd = 0; dd < 16; ++dd)
                    ag = fmaf(v_s[i * 256 + oo * 16 + dd], act_s[oo * 16 + dd], ag);
                logit_s[t] += ag;
            }
            __syncthreads();
        }
    }

    out[(size_t)pix * 256 + t] = act;
}

extern "C" void kernel_launch(void* const* d_in, const int* in_sizes, int n_in,
                              void* d_out, int out_size) {
    const float* x  = (const float*)d_in[0];
    const float* Wt = (const float*)d_in[1];
    const float* b  = (const float*)d_in[2];
    float* out = (float*)d_out;

    conv_kernel<<<128 * 32, 256>>>(x, Wt);       // 4096 blocks
    routing_kernel<<<16 * 32 * 32, 256>>>(b, out);  // 16384 blocks
}

// round 4
// speedup vs baseline: 1.5953x; 1.5953x over previous
#include <cuda_runtime.h>
#include <cuda_bf16.h>
#include <cstdint>
#include <cstddef>

// ---------------------------------------------------------------------------
//  x: [16, 32, 32, 8, 16]  (B,H,W,I,Din) fp32
//  W: [5, 5, 16, 256]      (kh,kw,cin,co) fp32, co = o*16+d
//  b: [1, 1, 16, 16]       fp32
//  out: [16, 32, 32, 16, 16] (B,H,W,O,D) fp32
//
// Routing group p uses conv images n = 8p+q -> input capsule i = p>>1 fixed,
// b_img = 8*(p&1)+q (the reference's I-major reshape).  CTA = (p, h, 16 w's):
// M=128 GEMM rows (8 q x 16 w) = exactly the votes its 16 routing points need.
// GEMM: M=128, N=256, K=400 (25 taps x 16 cin), k-steps of 16.
// bf16x3 split (x0w0 + x1w0 + x0w1) emulates fp32 to ~2^-16.
// ---------------------------------------------------------------------------

__device__ __nv_bfloat16 g_xs[2][16 * 32 * 32 * 8 * 16];   // pre-split x
__device__ __nv_bfloat16 g_ws[2][25 * 256 * 16];           // W as [k][n][16k]

// smem: 2 stages x (A[2 splits]128x48B + B[2 splits]256x48B) = 2 x 36864
#define ST_BYTES   36864
#define OFF_LOGIT  132096
#define OFF_ROUTE  132608
#define SMEM_ALLOC 133632

__device__ __forceinline__ uint32_t smem_u32(const void* p) {
    uint32_t a;
    asm("{ .reg .u64 t; cvta.to.shared.u64 t, %1; cvt.u32.u64 %0, t; }" : "=r"(a) : "l"(p));
    return a;
}
__device__ __forceinline__ void cp16z(uint32_t dst, const void* src, bool valid) {
    int sz = valid ? 16 : 0;
    asm volatile("cp.async.cg.shared.global [%0], [%1], 16, %2;\n"
                 :: "r"(dst), "l"(src), "r"(sz));
}
__device__ __forceinline__ void cp16(uint32_t dst, const void* src) {
    asm volatile("cp.async.cg.shared.global [%0], [%1], 16;\n" :: "r"(dst), "l"(src));
}
#define CP_COMMIT() asm volatile("cp.async.commit_group;\n")
#define CP_WAIT(n)  asm volatile("cp.async.wait_group %0;\n" :: "n"(n))

#define LDSM4(r, addr) \
    asm volatile("ldmatrix.sync.aligned.m8n8.x4.shared.b16 {%0,%1,%2,%3}, [%4];" \
                 : "=r"((r)[0]), "=r"((r)[1]), "=r"((r)[2]), "=r"((r)[3]) : "r"(addr))

#define MMA16816(c, a, bb0, bb1) \
    asm volatile("mma.sync.aligned.m16n8k16.row.col.f32.bf16.bf16.f32 " \
                 "{%0,%1,%2,%3}, {%4,%5,%6,%7}, {%8,%9}, {%0,%1,%2,%3};" \
                 : "+f"((c)[0]), "+f"((c)[1]), "+f"((c)[2]), "+f"((c)[3]) \
                 : "r"((a)[0]), "r"((a)[1]), "r"((a)[2]), "r"((a)[3]), \
                   "r"(bb0), "r"(bb1))

// ---------------- prep kernels ----------------
__global__ void xsplit_kernel(const float* __restrict__ x) {
    int idx = blockIdx.x * 256 + threadIdx.x;
    if (idx >= 16 * 32 * 32 * 8 * 16) return;
    float f = x[idx];
    __nv_bfloat16 t0 = __float2bfloat16_rn(f);
    __nv_bfloat16 t1 = __float2bfloat16_rn(f - __bfloat162float(t0));
    g_xs[0][idx] = t0;
    g_xs[1][idx] = t1;
}

__global__ void wsplit_kernel(const float* __restrict__ W) {
    int idx = blockIdx.x * 256 + threadIdx.x;   // k*256 + co
    if (idx >= 25 * 256) return;
    int co = idx & 255, k = idx >> 8;
#pragma unroll
    for (int cin = 0; cin < 16; ++cin) {
        float f = W[(k * 16 + cin) * 256 + co];
        __nv_bfloat16 t0 = __float2bfloat16_rn(f);
        __nv_bfloat16 t1 = __float2bfloat16_rn(f - __bfloat162float(t0));
        g_ws[0][idx * 16 + cin] = t0;
        g_ws[1][idx * 16 + cin] = t1;
    }
}

// ---------------- main fused kernel ----------------
__device__ __forceinline__ void load_tiles(uint32_t sbase, int k, int s2,
                                           int h, int w0, int i_true, int b_base,
                                           int t) {
    const int kh = k / 5, kw = k - kh * 5;
    const uint32_t stg = sbase + s2 * ST_BYTES;
    // A: 512 x 16B  (row = q*16+wl, 2 splits, 2 halves)
#pragma unroll
    for (int it = 0; it < 2; ++it) {
        int j = t + it * 256;
        int sp = j & 1, half = (j >> 1) & 1, row = j >> 2;
        int q = row >> 4, wl = row & 15;
        int hh = h + kh - 2, ww = w0 + wl + kw - 2;
        bool valid = ((unsigned)hh < 32u) && ((unsigned)ww < 32u);
        const __nv_bfloat16* src = valid
            ? &g_xs[sp][((((size_t)(b_base + q) * 32 + hh) * 32 + ww) * 8 + i_true) * 16 + half * 8]
            : &g_xs[0][0];
        cp16z(stg + sp * 6144 + row * 48 + half * 16, src, valid);
    }
    // B: 1024 x 16B (n-rows, 2 splits, 2 halves)
#pragma unroll
    for (int it = 0; it < 4; ++it) {
        int j = t + it * 256;
        int sp = j & 1, half = (j >> 1) & 1, n = j >> 2;
        cp16(stg + 12288 + sp * 12288 + n * 48 + half * 16,
             &g_ws[sp][((size_t)k * 256 + n) * 16 + half * 8]);
    }
}

__global__ __launch_bounds__(256, 1) void caps_fused_kernel(
    const float* __restrict__ bias, float* __restrict__ out) {
    extern __shared__ __align__(1024) char sm[];
    const uint32_t sbase = smem_u32(sm);

    const int t = threadIdx.x;
    const int wid = t >> 5, lane = t & 31;
    const int bid = blockIdx.x;
    const int wb = bid & 1, h = (bid >> 1) & 31, p = bid >> 6;
    const int w0 = wb * 16;
    const int i_true = p >> 1, b_base = (p & 1) * 8;

    const int wm = wid & 1;        // m block (64 rows)
    const int wn = wid >> 1;       // n block (64 cols)

    // ldmatrix lane address components
    const uint32_t a_row  = lane & 15;
    const uint32_t a_koff = (lane >> 4) * 16;
    const uint32_t b_row  = (lane & 7) + ((lane >> 4) << 3);
    const uint32_t b_koff = ((lane >> 3) & 1) * 16;

    float acc[4][8][4];
#pragma unroll
    for (int mi = 0; mi < 4; ++mi)
#pragma unroll
        for (int ni = 0; ni < 8; ++ni)
#pragma unroll
            for (int j = 0; j < 4; ++j) acc[mi][ni][j] = 0.f;

    load_tiles(sbase, 0, 0, h, w0, i_true, b_base, t);
    CP_COMMIT();

    for (int k = 0; k < 25; ++k) {
        const int s2 = k & 1;
        if (k + 1 < 25) {
            load_tiles(sbase, k + 1, s2 ^ 1, h, w0, i_true, b_base, t);
            CP_COMMIT();
            CP_WAIT(1);
        } else {
            CP_WAIT(0);
        }
        __syncthreads();

        const uint32_t stg = sbase + s2 * ST_BYTES;
        const uint32_t Ab = stg + (wm * 64 + a_row) * 48 + a_koff;
        const uint32_t Bb = stg + 12288 + (wn * 64 + b_row) * 48 + b_koff;

        uint32_t Af[4][4], Bf[4][4];
        // pass 1: x0 * w0
#pragma unroll
        for (int mi = 0; mi < 4; ++mi) LDSM4(Af[mi], Ab + mi * 768);
#pragma unroll
        for (int nt = 0; nt < 4; ++nt) LDSM4(Bf[nt], Bb + nt * 768);
#pragma unroll
        for (int mi = 0; mi < 4; ++mi)
#pragma unroll
            for (int nt = 0; nt < 4; ++nt) {
                MMA16816(acc[mi][2 * nt],     Af[mi], Bf[nt][0], Bf[nt][1]);
                MMA16816(acc[mi][2 * nt + 1], Af[mi], Bf[nt][2], Bf[nt][3]);
            }
        // pass 2: x1 * w0
#pragma unroll
        for (int mi = 0; mi < 4; ++mi) LDSM4(Af[mi], Ab + 6144 + mi * 768);
#pragma unroll
        for (int mi = 0; mi < 4; ++mi)
#pragma unroll
            for (int nt = 0; nt < 4; ++nt) {
                MMA16816(acc[mi][2 * nt],     Af[mi], Bf[nt][0], Bf[nt][1]);
                MMA16816(acc[mi][2 * nt + 1], Af[mi], Bf[nt][2], Bf[nt][3]);
            }
        // pass 3: x0 * w1
#pragma unroll
        for (int mi = 0; mi < 4; ++mi) LDSM4(Af[mi], Ab + mi * 768);
#pragma unroll
        for (int nt = 0; nt < 4; ++nt) LDSM4(Bf[nt], Bb + 12288 + nt * 768);
#pragma unroll
        for (int mi = 0; mi < 4; ++mi)
#pragma unroll
            for (int nt = 0; nt < 4; ++nt) {
                MMA16816(acc[mi][2 * nt],     Af[mi], Bf[nt][0], Bf[nt][1]);
                MMA16816(acc[mi][2 * nt + 1], Af[mi], Bf[nt][2], Bf[nt][3]);
            }
        __syncthreads();
    }

    // ---- dump accumulators to smem votes: Dsm[row 128][col 256], stride 258 ----
    const float bval = bias[t];
    float* Dsm = (float*)sm;
    {
        const int g = lane >> 2, tq = lane & 3;
#pragma unroll
        for (int mi = 0; mi < 4; ++mi)
#pragma unroll
            for (int ni = 0; ni < 8; ++ni) {
                int row = wm * 64 + mi * 16 + g;
                int col = wn * 64 + ni * 8 + tq * 2;
                *(float2*)&Dsm[(size_t)row * 258 + col] =
                    make_float2(acc[mi][ni][0], acc[mi][ni][1]);
                *(float2*)&Dsm[(size_t)(row + 8) * 258 + col] =
                    make_float2(acc[mi][ni][2], acc[mi][ni][3]);
            }
    }
    __syncthreads();

    // ---- fused routing: 16 points, 3 iterations ----
    float* logit = (float*)(sm + OFF_LOGIT);   // [q][o] 128
    float* route = (float*)(sm + OFF_ROUTE);   // [q][o] 128
    const int o = t >> 4, d = t & 15;

    for (int pt = 0; pt < 16; ++pt) {
        float vq[8];
#pragma unroll
        for (int q = 0; q < 8; ++q)
            vq[q] = Dsm[(size_t)(q * 16 + pt) * 258 + t];

        // iter 0: softmax(0) = 1/16
        float pre = bval;
#pragma unroll
        for (int q = 0; q < 8; ++q) pre = fmaf(0.0625f, vq[q], pre);
        float sq = pre * pre;
#pragma unroll
        for (int st = 8; st; st >>= 1)
            sq += __shfl_xor_sync(0xffffffffu, sq, st, 16);
        float act = pre * sqrtf(sq) / (1.f + sq);

        {   // agreement -> logits (initial logits are 0, so plain store)
            float r[8];
#pragma unroll
            for (int q = 0; q < 8; ++q) r[q] = vq[q] * act;
#pragma unroll
            for (int st = 8; st; st >>= 1)
#pragma unroll
                for (int q = 0; q < 8; ++q)
                    r[q] += __shfl_xor_sync(0xffffffffu, r[q], st, 16);
            if (d < 8) {
                float val = r[0];
#pragma unroll
                for (int q = 1; q < 8; ++q) if (d == q) val = r[q];
                logit[d * 16 + o] = val;
            }
        }
        __syncthreads();

#pragma unroll
        for (int it = 1; it < 3; ++it) {
            if (t < 128) {          // softmax over o, per input capsule
                float l = logit[t];
                float mx = l;
#pragma unroll
                for (int st = 8; st; st >>= 1)
                    mx = fmaxf(mx, __shfl_xor_sync(0xffffffffu, mx, st, 16));
                float e = __expf(l - mx);
                float sum = e;
#pragma unroll
                for (int st = 8; st; st >>= 1)
                    sum += __shfl_xor_sync(0xffffffffu, sum, st, 16);
                route[t] = e / sum;
            }
            __syncthreads();

            pre = bval;
#pragma unroll
            for (int q = 0; q < 8; ++q)
                pre = fmaf(route[q * 16 + o], vq[q], pre);
            sq = pre * pre;
#pragma unroll
            for (int st = 8; st; st >>= 1)
                sq += __shfl_xor_sync(0xffffffffu, sq, st, 16);
            act = pre * sqrtf(sq) / (1.f + sq);

            if (it == 1) {
                float r[8];
#pragma unroll
                for (int q = 0; q < 8; ++q) r[q] = vq[q] * act;
#pragma unroll
                for (int st = 8; st; st >>= 1)
#pragma unroll
                    for (int q = 0; q < 8; ++q)
                        r[q] += __shfl_xor_sync(0xffffffffu, r[q], st, 16);
                if (d < 8) {
                    float val = r[0];
#pragma unroll
                    for (int q = 1; q < 8; ++q) if (d == q) val = r[q];
                    logit[d * 16 + o] += val;
                }
                __syncthreads();
            }
        }

        out[(((size_t)p * 32 + h) * 32 + (w0 + pt)) * 256 + t] = act;
        __syncthreads();
    }
}

extern "C" void kernel_launch(void* const* d_in, const int* in_sizes, int n_in,
                              void* d_out, int out_size) {
    const float* x  = (const float*)d_in[0];
    const float* Wt = (const float*)d_in[1];
    const float* b  = (const float*)d_in[2];
    float* out = (float*)d_out;

    cudaFuncSetAttribute(caps_fused_kernel,
                         cudaFuncAttributeMaxDynamicSharedMemorySize, SMEM_ALLOC);

    xsplit_kernel<<<8192, 256>>>(x);
    wsplit_kernel<<<25, 256>>>(Wt);
    caps_fused_kernel<<<1024, 256, SMEM_ALLOC>>>(b, out);
}

// round 5
// speedup vs baseline: 1.9549x; 1.2254x over previous
#include <cuda_runtime.h>
#include <cuda_bf16.h>
#include <cstdint>
#include <cstddef>

// ---------------------------------------------------------------------------
//  x: [16, 32, 32, 8, 16]  (B,H,W,I,Din) fp32
//  W: [5, 5, 16, 256]      (kh,kw,cin,co) fp32, co = o*16+d
//  b: [1, 1, 16, 16]       fp32
//  out: [16, 32, 32, 16, 16] (B,H,W,O,D) fp32
//
// Routing group p uses conv images n = 8p+q -> input capsule i = p>>1 fixed,
// b_img = 8*(p&1)+q.  CTA = (p, h, 16 w's): M=128 GEMM rows = exactly the
// votes its 16 routing points need.  GEMM: M=128, N=256, K=400 in k16 steps.
// bf16x3 split (x0w0 + x1w0 + x0w1) emulates fp32 to ~2^-17.
// 512 threads, 16 warps, warp tile m32n64, 3-stage cp.async, 1 sync/step.
// ---------------------------------------------------------------------------

__device__ __nv_bfloat16 g_xs[2][16 * 32 * 32 * 8 * 16];   // pre-split x
__device__ __nv_bfloat16 g_ws[2][25 * 256 * 16];           // W as [k][n][16k]

// stage: A[2 splits]128x48B (12288) + B[2 splits]256x48B (24576) = 36864
#define ST_BYTES   36864
#define OFF_LOGIT  132096          // 2 groups x 128 f32
#define OFF_ROUTE  133120          // 2 groups x 128 f32
#define SMEM_ALLOC 134144

__device__ __forceinline__ uint32_t smem_u32(const void* p) {
    uint32_t a;
    asm("{ .reg .u64 t; cvta.to.shared.u64 t, %1; cvt.u32.u64 %0, t; }" : "=r"(a) : "l"(p));
    return a;
}
__device__ __forceinline__ void cp16z(uint32_t dst, const void* src, bool valid) {
    int sz = valid ? 16 : 0;
    asm volatile("cp.async.cg.shared.global [%0], [%1], 16, %2;\n"
                 :: "r"(dst), "l"(src), "r"(sz));
}
__device__ __forceinline__ void cp16(uint32_t dst, const void* src) {
    asm volatile("cp.async.cg.shared.global [%0], [%1], 16;\n" :: "r"(dst), "l"(src));
}
#define CP_COMMIT() asm volatile("cp.async.commit_group;\n")
#define CP_WAIT(n)  asm volatile("cp.async.wait_group %0;\n" :: "n"(n))

#define LDSM4(r, addr) \
    asm volatile("ldmatrix.sync.aligned.m8n8.x4.shared.b16 {%0,%1,%2,%3}, [%4];" \
                 : "=r"((r)[0]), "=r"((r)[1]), "=r"((r)[2]), "=r"((r)[3]) : "r"(addr))

#define MMA16816(c, a, bb0, bb1) \
    asm volatile("mma.sync.aligned.m16n8k16.row.col.f32.bf16.bf16.f32 " \
                 "{%0,%1,%2,%3}, {%4,%5,%6,%7}, {%8,%9}, {%0,%1,%2,%3};" \
                 : "+f"((c)[0]), "+f"((c)[1]), "+f"((c)[2]), "+f"((c)[3]) \
                 : "r"((a)[0]), "r"((a)[1]), "r"((a)[2]), "r"((a)[3]), \
                   "r"(bb0), "r"(bb1))

// ---------------- prep kernels ----------------
__global__ void xsplit_kernel(const float* __restrict__ x) {
    int idx = blockIdx.x * 256 + threadIdx.x;          // 4 floats per thread
    if (idx >= 16 * 32 * 32 * 8 * 16 / 4) return;
    float4 f = ((const float4*)x)[idx];
    __nv_bfloat16 h0[4], h1[4];
    float v[4] = {f.x, f.y, f.z, f.w};
#pragma unroll
    for (int j = 0; j < 4; ++j) {
        h0[j] = __float2bfloat16_rn(v[j]);
        h1[j] = __float2bfloat16_rn(v[j] - __bfloat162float(h0[j]));
    }
    *(uint2*)&g_xs[0][idx * 4] = *(uint2*)h0;
    *(uint2*)&g_xs[1][idx * 4] = *(uint2*)h1;
}

__global__ void wsplit_kernel(const float* __restrict__ W) {
    int idx = blockIdx.x * 256 + threadIdx.x;   // k*256 + co
    if (idx >= 25 * 256) return;
    int co = idx & 255, k = idx >> 8;
#pragma unroll
    for (int cin = 0; cin < 16; ++cin) {
        float f = W[(k * 16 + cin) * 256 + co];
        __nv_bfloat16 t0 = __float2bfloat16_rn(f);
        __nv_bfloat16 t1 = __float2bfloat16_rn(f - __bfloat162float(t0));
        g_ws[0][idx * 16 + cin] = t0;
        g_ws[1][idx * 16 + cin] = t1;
    }
}

// ---------------- main fused kernel ----------------
__device__ __forceinline__ void load_tiles(uint32_t sbase, int k, int stg_i,
                                           int h, int w0, int i_true, int b_base,
                                           int t) {
    const int kh = k / 5, kw = k - kh * 5;
    const uint32_t stg = sbase + stg_i * ST_BYTES;
    // A: 512 x 16B  (1 per thread)
    {
        int j = t;
        int sp = j & 1, half = (j >> 1) & 1, row = j >> 2;
        int q = row >> 4, wl = row & 15;
        int hh = h + kh - 2, ww = w0 + wl + kw - 2;
        bool valid = ((unsigned)hh < 32u) && ((unsigned)ww < 32u);
        const __nv_bfloat16* src = valid
            ? &g_xs[sp][((((size_t)(b_base + q) * 32 + hh) * 32 + ww) * 8 + i_true) * 16 + half * 8]
            : &g_xs[0][0];
        cp16z(stg + sp * 6144 + row * 48 + half * 16, src, valid);
    }
    // B: 1024 x 16B (2 per thread)
#pragma unroll
    for (int it = 0; it < 2; ++it) {
        int j = t + it * 512;
        int sp = j & 1, half = (j >> 1) & 1, n = j >> 2;
        cp16(stg + 12288 + sp * 12288 + n * 48 + half * 16,
             &g_ws[sp][((size_t)k * 256 + n) * 16 + half * 8]);
    }
}

__global__ __launch_bounds__(512, 1) void caps_fused_kernel(
    const float* __restrict__ bias, float* __restrict__ out) {
    extern __shared__ __align__(1024) char sm[];
    const uint32_t sbase = smem_u32(sm);

    const int t = threadIdx.x;
    const int wid = t >> 5, lane = t & 31;
    const int bid = blockIdx.x;
    const int wb = bid & 1, h = (bid >> 1) & 31, p = bid >> 6;
    const int w0 = wb * 16;
    const int i_true = p >> 1, b_base = (p & 1) * 8;

    const int wm = wid & 3;        // m block (32 rows each)
    const int wn = wid >> 2;       // n block (64 cols each)

    // ldmatrix lane address components
    const uint32_t a_row  = lane & 15;
    const uint32_t a_koff = (lane >> 4) * 16;
    const uint32_t b_row  = (lane & 7) + ((lane >> 4) << 3);
    const uint32_t b_koff = ((lane >> 3) & 1) * 16;

    float acc[2][8][4];
#pragma unroll
    for (int mi = 0; mi < 2; ++mi)
#pragma unroll
        for (int ni = 0; ni < 8; ++ni)
#pragma unroll
            for (int j = 0; j < 4; ++j) acc[mi][ni][j] = 0.f;

    // prologue: stages 0,1
    load_tiles(sbase, 0, 0, h, w0, i_true, b_base, t);
    CP_COMMIT();
    load_tiles(sbase, 1, 1, h, w0, i_true, b_base, t);
    CP_COMMIT();

    int stg_i = 0;
    for (int k = 0; k < 25; ++k) {
        if (k < 24) CP_WAIT(1); else CP_WAIT(0);
        __syncthreads();                     // stage k ready; stage (k-1)%3 free
        if (k + 2 < 25) {
            load_tiles(sbase, k + 2, (stg_i + 2) % 3, h, w0, i_true, b_base, t);
            CP_COMMIT();
        }

        const uint32_t stg = sbase + stg_i * ST_BYTES;
        const uint32_t Ab = stg + (wm * 32 + a_row) * 48 + a_koff;
        const uint32_t Bb = stg + 12288 + (wn * 64 + b_row) * 48 + b_koff;

        uint32_t Af[2][4], Bf[4][4];
        // pass 1: x0 * w0
#pragma unroll
        for (int mi = 0; mi < 2; ++mi) LDSM4(Af[mi], Ab + mi * 768);
#pragma unroll
        for (int nt = 0; nt < 4; ++nt) LDSM4(Bf[nt], Bb + nt * 768);
#pragma unroll
        for (int mi = 0; mi < 2; ++mi)
#pragma unroll
            for (int nt = 0; nt < 4; ++nt) {
                MMA16816(acc[mi][2 * nt],     Af[mi], Bf[nt][0], Bf[nt][1]);
                MMA16816(acc[mi][2 * nt + 1], Af[mi], Bf[nt][2], Bf[nt][3]);
            }
        // pass 2: x1 * w0
#pragma unroll
        for (int mi = 0; mi < 2; ++mi) LDSM4(Af[mi], Ab + 6144 + mi * 768);
#pragma unroll
        for (int mi = 0; mi < 2; ++mi)
#pragma unroll
            for (int nt = 0; nt < 4; ++nt) {
                MMA16816(acc[mi][2 * nt],     Af[mi], Bf[nt][0], Bf[nt][1]);
                MMA16816(acc[mi][2 * nt + 1], Af[mi], Bf[nt][2], Bf[nt][3]);
            }
        // pass 3: x0 * w1
#pragma unroll
        for (int mi = 0; mi < 2; ++mi) LDSM4(Af[mi], Ab + mi * 768);
#pragma unroll
        for (int nt = 0; nt < 4; ++nt) LDSM4(Bf[nt], Bb + 12288 + nt * 768);
#pragma unroll
        for (int mi = 0; mi < 2; ++mi)
#pragma unroll
            for (int nt = 0; nt < 4; ++nt) {
                MMA16816(acc[mi][2 * nt],     Af[mi], Bf[nt][0], Bf[nt][1]);
                MMA16816(acc[mi][2 * nt + 1], Af[mi], Bf[nt][2], Bf[nt][3]);
            }

        stg_i = (stg_i + 1) % 3;
    }
    __syncthreads();   // all compute done; stage smem now dead -> vote dump

    // ---- dump accumulators: Dsm[row 128][col 256], stride 258 ----
    float* Dsm = (float*)sm;
    {
        const int g = lane >> 2, tq = lane & 3;
#pragma unroll
        for (int mi = 0; mi < 2; ++mi)
#pragma unroll
            for (int ni = 0; ni < 8; ++ni) {
                int row = wm * 32 + mi * 16 + g;
                int col = wn * 64 + ni * 8 + tq * 2;
                *(float2*)&Dsm[(size_t)row * 258 + col] =
                    make_float2(acc[mi][ni][0], acc[mi][ni][1]);
                *(float2*)&Dsm[(size_t)(row + 8) * 258 + col] =
                    make_float2(acc[mi][ni][2], acc[mi][ni][3]);
            }
    }
    __syncthreads();

    // ---- fused routing: 16 points, 2 at a time (2 groups of 256 thr) ----
    float* logit = (float*)(sm + OFF_LOGIT);   // [g2][q*16+o]
    float* route = (float*)(sm + OFF_ROUTE);
    const int g2 = t >> 8, t2 = t & 255;
    const float bval = bias[t2];
    const int o = t2 >> 4, d = t2 & 15;
    float* lg = logit + g2 * 128;
    float* rt = route + g2 * 128;

    for (int step = 0; step < 8; ++step) {
        const int pt = step * 2 + g2;
        float vq[8];
#pragma unroll
        for (int q = 0; q < 8; ++q)
            vq[q] = Dsm[(size_t)(q * 16 + pt) * 258 + t2];

        // iter 0: softmax(0) = 1/16
        float pre = bval;
#pragma unroll
        for (int q = 0; q < 8; ++q) pre = fmaf(0.0625f, vq[q], pre);
        float sq = pre * pre;
#pragma unroll
        for (int st = 8; st; st >>= 1)
            sq += __shfl_xor_sync(0xffffffffu, sq, st, 16);
        float act = pre * sqrtf(sq) / (1.f + sq);

        {   // agreement -> logits (initial logits 0, plain store)
            float r[8];
#pragma unroll
            for (int q = 0; q < 8; ++q) r[q] = vq[q] * act;
#pragma unroll
            for (int st = 8; st; st >>= 1)
#pragma unroll
                for (int q = 0; q < 8; ++q)
                    r[q] += __shfl_xor_sync(0xffffffffu, r[q], st, 16);
            if (d < 8) {
                float val = r[0];
#pragma unroll
                for (int q = 1; q < 8; ++q) if (d == q) val = r[q];
                lg[d * 16 + o] = val;
            }
        }
        __syncthreads();

#pragma unroll
        for (int it = 1; it < 3; ++it) {
            if (t2 < 128) {          // softmax over o, per input capsule
                float l = lg[t2];
                float mx = l;
#pragma unroll
                for (int st = 8; st; st >>= 1)
                    mx = fmaxf(mx, __shfl_xor_sync(0xffffffffu, mx, st, 16));
                float e = __expf(l - mx);
                float sum = e;
#pragma unroll
                for (int st = 8; st; st >>= 1)
                    sum += __shfl_xor_sync(0xffffffffu, sum, st, 16);
                rt[t2] = e / sum;
            }
            __syncthreads();

            pre = bval;
#pragma unroll
            for (int q = 0; q < 8; ++q)
                pre = fmaf(rt[q * 16 + o], vq[q], pre);
            sq = pre * pre;
#pragma unroll
            for (int st = 8; st; st >>= 1)
                sq += __shfl_xor_sync(0xffffffffu, sq, st, 16);
            act = pre * sqrtf(sq) / (1.f + sq);

            if (it == 1) {
                float r[8];
#pragma unroll
                for (int q = 0; q < 8; ++q) r[q] = vq[q] * act;
#pragma unroll
                for (int st = 8; st; st >>= 1)
#pragma unroll
                    for (int q = 0; q < 8; ++q)
                        r[q] += __shfl_xor_sync(0xffffffffu, r[q], st, 16);
                if (d < 8) {
                    float val = r[0];
#pragma unroll
                    for (int q = 1; q < 8; ++q) if (d == q) val = r[q];
                    lg[d * 16 + o] += val;
                }
                __syncthreads();
            }
        }

        out[(((size_t)p * 32 + h) * 32 + (w0 + pt)) * 256 + t2] = act;
        __syncthreads();
    }
}

extern "C" void kernel_launch(void* const* d_in, const int* in_sizes, int n_in,
                              void* d_out, int out_size) {
    const float* x  = (const float*)d_in[0];
    const float* Wt = (const float*)d_in[1];
    const float* b  = (const float*)d_in[2];
    float* out = (float*)d_out;

    cudaFuncSetAttribute(caps_fused_kernel,
                         cudaFuncAttributeMaxDynamicSharedMemorySize, SMEM_ALLOC);

    xsplit_kernel<<<2048, 256>>>(x);
    wsplit_kernel<<<25, 256>>>(Wt);
    caps_fused_kernel<<<1024, 512, SMEM_ALLOC>>>(b, out);
}

// round 6
// speedup vs baseline: 2.4786x; 1.2679x over previous
#include <cuda_runtime.h>
#include <cuda_fp16.h>
#include <cstdint>
#include <cstddef>

// ---------------------------------------------------------------------------
//  x: [16, 32, 32, 8, 16]  (B,H,W,I,Din) fp32
//  W: [5, 5, 16, 256]      (kh,kw,cin,co) fp32, co = o*16+d
//  b: [1, 1, 16, 16]       fp32
//  out: [16, 32, 32, 16, 16] (B,H,W,O,D) fp32
//
// Routing group p uses conv images n = 8p+q -> input capsule i = p>>1 fixed,
// b_img = 8*(p&1)+q.  CTA = (p, h, 16 w's): M=128 GEMM rows = exactly the
// votes its 16 routing points need.  GEMM: M=128, N=256, K=400 in k16 steps.
// fp16x2: x = x0+x1 (fp16 pair), W = fp16 single -> 2 MMA passes,
// error ~2^-12 from W rounding (tolerance 1e-3).
// 512 threads, 16 warps, warp tile m32n64, 4-stage cp.async, 1 sync/step.
// ---------------------------------------------------------------------------

__device__ __half g_xs[2][16 * 32 * 32 * 8 * 16];   // x split halves
__device__ __half g_ws[25 * 256 * 16];              // W as [k][n][16k], fp16

// stage: A[2 splits] 128x48B (12288) + B 256x48B (12288) = 24576
#define ST_BYTES   24576
#define OFF_LOGIT  132096          // 2 groups x 128 f32
#define OFF_ROUTE  133120
#define SMEM_ALLOC 134144

__device__ __forceinline__ uint32_t smem_u32(const void* p) {
    uint32_t a;
    asm("{ .reg .u64 t; cvta.to.shared.u64 t, %1; cvt.u32.u64 %0, t; }" : "=r"(a) : "l"(p));
    return a;
}
__device__ __forceinline__ void cp16z(uint32_t dst, const void* src, bool valid) {
    int sz = valid ? 16 : 0;
    asm volatile("cp.async.cg.shared.global [%0], [%1], 16, %2;\n"
                 :: "r"(dst), "l"(src), "r"(sz));
}
__device__ __forceinline__ void cp16(uint32_t dst, const void* src) {
    asm volatile("cp.async.cg.shared.global [%0], [%1], 16;\n" :: "r"(dst), "l"(src));
}
#define CP_COMMIT() asm volatile("cp.async.commit_group;\n")
#define CP_WAIT(n)  asm volatile("cp.async.wait_group %0;\n" :: "n"(n))

#define LDSM4(r, addr) \
    asm volatile("ldmatrix.sync.aligned.m8n8.x4.shared.b16 {%0,%1,%2,%3}, [%4];" \
                 : "=r"((r)[0]), "=r"((r)[1]), "=r"((r)[2]), "=r"((r)[3]) : "r"(addr))

#define MMA16816(c, a, bb0, bb1) \
    asm volatile("mma.sync.aligned.m16n8k16.row.col.f32.f16.f16.f32 " \
                 "{%0,%1,%2,%3}, {%4,%5,%6,%7}, {%8,%9}, {%0,%1,%2,%3};" \
                 : "+f"((c)[0]), "+f"((c)[1]), "+f"((c)[2]), "+f"((c)[3]) \
                 : "r"((a)[0]), "r"((a)[1]), "r"((a)[2]), "r"((a)[3]), \
                   "r"(bb0), "r"(bb1))

// ---------------- prep kernels ----------------
__global__ void xsplit_kernel(const float* __restrict__ x) {
    int idx = blockIdx.x * 256 + threadIdx.x;          // 4 floats per thread
    if (idx >= 16 * 32 * 32 * 8 * 16 / 4) return;
    float4 f = ((const float4*)x)[idx];
    __half h0[4], h1[4];
    float v[4] = {f.x, f.y, f.z, f.w};
#pragma unroll
    for (int j = 0; j < 4; ++j) {
        h0[j] = __float2half_rn(v[j]);
        h1[j] = __float2half_rn(v[j] - __half2float(h0[j]));
    }
    *(uint2*)&g_xs[0][idx * 4] = *(uint2*)h0;
    *(uint2*)&g_xs[1][idx * 4] = *(uint2*)h1;
}

__global__ void wsplit_kernel(const float* __restrict__ W) {
    int idx = blockIdx.x * 256 + threadIdx.x;   // k*256 + co
    if (idx >= 25 * 256) return;
    int co = idx & 255, k = idx >> 8;
#pragma unroll
    for (int cin = 0; cin < 16; ++cin)
        g_ws[idx * 16 + cin] = __float2half_rn(W[(k * 16 + cin) * 256 + co]);
}

// ---------------- main fused kernel ----------------
__device__ __forceinline__ void load_tiles(uint32_t sbase, int k, int stg_i,
                                           int h, int w0, int i_true, int b_base,
                                           int t) {
    const int kh = k / 5, kw = k - kh * 5;
    const uint32_t stg = sbase + stg_i * ST_BYTES;
    // A: 512 x 16B (1 per thread): half(2) x row(128) x split(2)
    {
        int half = t & 1, row = (t >> 1) & 127, sp = t >> 8;
        int q = row >> 4, wl = row & 15;
        int hh = h + kh - 2, ww = w0 + wl + kw - 2;
        bool valid = ((unsigned)hh < 32u) && ((unsigned)ww < 32u);
        const __half* src = valid
            ? &g_xs[sp][((((size_t)(b_base + q) * 32 + hh) * 32 + ww) * 8 + i_true) * 16 + half * 8]
            : &g_xs[0][0];
        cp16z(stg + sp * 6144 + row * 48 + half * 16, src, valid);
    }
    // B: 512 x 16B (1 per thread): half(2) x n(256)
    {
        int half = t & 1, n = t >> 1;
        cp16(stg + 12288 + n * 48 + half * 16,
             &g_ws[((size_t)k * 256 + n) * 16 + half * 8]);
    }
}

__global__ __launch_bounds__(512, 1) void caps_fused_kernel(
    const float* __restrict__ bias, float* __restrict__ out) {
    extern __shared__ __align__(1024) char sm[];
    const uint32_t sbase = smem_u32(sm);

    const int t = threadIdx.x;
    const int wid = t >> 5, lane = t & 31;
    const int bid = blockIdx.x;
    const int wb = bid & 1, h = (bid >> 1) & 31, p = bid >> 6;
    const int w0 = wb * 16;
    const int i_true = p >> 1, b_base = (p & 1) * 8;

    const int wm = wid & 3;        // m block (32 rows each)
    const int wn = wid >> 2;       // n block (64 cols each)

    const uint32_t a_row  = lane & 15;
    const uint32_t a_koff = (lane >> 4) * 16;
    const uint32_t b_row  = (lane & 7) + ((lane >> 4) << 3);
    const uint32_t b_koff = ((lane >> 3) & 1) * 16;

    float acc[2][8][4];
#pragma unroll
    for (int mi = 0; mi < 2; ++mi)
#pragma unroll
        for (int ni = 0; ni < 8; ++ni)
#pragma unroll
            for (int j = 0; j < 4; ++j) acc[mi][ni][j] = 0.f;

    // prologue: stages 0,1,2
#pragma unroll
    for (int s = 0; s < 3; ++s) {
        load_tiles(sbase, s, s, h, w0, i_true, b_base, t);
        CP_COMMIT();
    }

    for (int k = 0; k < 25; ++k) {
        const int stg_i = k & 3;
        if (k <= 22) CP_WAIT(2); else if (k == 23) CP_WAIT(1); else CP_WAIT(0);
        __syncthreads();                 // stage k ready; stage (k-1)&3 free
        if (k + 3 < 25) {
            load_tiles(sbase, k + 3, (k + 3) & 3, h, w0, i_true, b_base, t);
            CP_COMMIT();
        }

        const uint32_t stg = sbase + stg_i * ST_BYTES;
        const uint32_t Ab = stg + (wm * 32 + a_row) * 48 + a_koff;
        const uint32_t Bb = stg + 12288 + (wn * 64 + b_row) * 48 + b_koff;

        uint32_t Af[2][4], Bf[4][4];
        // pass 1: x0 * w
#pragma unroll
        for (int mi = 0; mi < 2; ++mi) LDSM4(Af[mi], Ab + mi * 768);
#pragma unroll
        for (int nt = 0; nt < 4; ++nt) LDSM4(Bf[nt], Bb + nt * 768);
#pragma unroll
        for (int mi = 0; mi < 2; ++mi)
#pragma unroll
            for (int nt = 0; nt < 4; ++nt) {
                MMA16816(acc[mi][2 * nt],     Af[mi], Bf[nt][0], Bf[nt][1]);
                MMA16816(acc[mi][2 * nt + 1], Af[mi], Bf[nt][2], Bf[nt][3]);
            }
        // pass 2: x1 * w
#pragma unroll
        for (int mi = 0; mi < 2; ++mi) LDSM4(Af[mi], Ab + 6144 + mi * 768);
#pragma unroll
        for (int mi = 0; mi < 2; ++mi)
#pragma unroll
            for (int nt = 0; nt < 4; ++nt) {
                MMA16816(acc[mi][2 * nt],     Af[mi], Bf[nt][0], Bf[nt][1]);
                MMA16816(acc[mi][2 * nt + 1], Af[mi], Bf[nt][2], Bf[nt][3]);
            }
    }
    __syncthreads();   // compute done; stage smem dead -> vote dump

    // ---- dump accumulators: Dsm[row 128][col 256], stride 258 ----
    float* Dsm = (float*)sm;
    {
        const int g = lane >> 2, tq = lane & 3;
#pragma unroll
        for (int mi = 0; mi < 2; ++mi)
#pragma unroll
            for (int ni = 0; ni < 8; ++ni) {
                int row = wm * 32 + mi * 16 + g;
                int col = wn * 64 + ni * 8 + tq * 2;
                *(float2*)&Dsm[(size_t)row * 258 + col] =
                    make_float2(acc[mi][ni][0], acc[mi][ni][1]);
                *(float2*)&Dsm[(size_t)(row + 8) * 258 + col] =
                    make_float2(acc[mi][ni][2], acc[mi][ni][3]);
            }
    }
    __syncthreads();

    // ---- fused routing: 16 points, 2 at a time (2 groups of 256 thr) ----
    float* logit = (float*)(sm + OFF_LOGIT);
    float* route = (float*)(sm + OFF_ROUTE);
    const int g2 = t >> 8, t2 = t & 255;
    const float bval = bias[t2];
    const int o = t2 >> 4, d = t2 & 15;
    float* lg = logit + g2 * 128;
    float* rt = route + g2 * 128;

    for (int step = 0; step < 8; ++step) {
        const int pt = step * 2 + g2;
        float vq[8];
#pragma unroll
        for (int q = 0; q < 8; ++q)
            vq[q] = Dsm[(size_t)(q * 16 + pt) * 258 + t2];

        // iter 0: softmax(0) = 1/16
        float pre = bval;
#pragma unroll
        for (int q = 0; q < 8; ++q) pre = fmaf(0.0625f, vq[q], pre);
        float sq = pre * pre;
#pragma unroll
        for (int st = 8; st; st >>= 1)
            sq += __shfl_xor_sync(0xffffffffu, sq, st, 16);
        float act = pre * sqrtf(sq) / (1.f + sq);

        {   // agreement -> logits (initial logits 0, plain store)
            float r[8];
#pragma unroll
            for (int q = 0; q < 8; ++q) r[q] = vq[q] * act;
#pragma unroll
            for (int st = 8; st; st >>= 1)
#pragma unroll
                for (int q = 0; q < 8; ++q)
                    r[q] += __shfl_xor_sync(0xffffffffu, r[q], st, 16);
            if (d < 8) {
                float val = r[0];
#pragma unroll
                for (int q = 1; q < 8; ++q) if (d == q) val = r[q];
                lg[d * 16 + o] = val;
            }
        }
        __syncthreads();

#pragma unroll
        for (int it = 1; it < 3; ++it) {
            if (t2 < 128) {
                float l = lg[t2];
                float mx = l;
#pragma unroll
                for (int st = 8; st; st >>= 1)
                    mx = fmaxf(mx, __shfl_xor_sync(0xffffffffu, mx, st, 16));
                float e = __expf(l - mx);
                float sum = e;
#pragma unroll
                for (int st = 8; st; st >>= 1)
                    sum += __shfl_xor_sync(0xffffffffu, sum, st, 16);
                rt[t2] = e / sum;
            }
            __syncthreads();

            pre = bval;
#pragma unroll
            for (int q = 0; q < 8; ++q)
                pre = fmaf(rt[q * 16 + o], vq[q], pre);
            sq = pre * pre;
#pragma unroll
            for (int st = 8; st; st >>= 1)
                sq += __shfl_xor_sync(0xffffffffu, sq, st, 16);
            act = pre * sqrtf(sq) / (1.f + sq);

            if (it == 1) {
                float r[8];
#pragma unroll
                for (int q = 0; q < 8; ++q) r[q] = vq[q] * act;
#pragma unroll
                for (int st = 8; st; st >>= 1)
#pragma unroll
                    for (int q = 0; q < 8; ++q)
                        r[q] += __shfl_xor_sync(0xffffffffu, r[q], st, 16);
                if (d < 8) {
                    float val = r[0];
#pragma unroll
                    for (int q = 1; q < 8; ++q) if (d == q) val = r[q];
                    lg[d * 16 + o] += val;
                }
                __syncthreads();
            }
        }

        out[(((size_t)p * 32 + h) * 32 + (w0 + pt)) * 256 + t2] = act;
        __syncthreads();
    }
}

extern "C" void kernel_launch(void* const* d_in, const int* in_sizes, int n_in,
                              void* d_out, int out_size) {
    const float* x  = (const float*)d_in[0];
    const float* Wt = (const float*)d_in[1];
    const float* b  = (const float*)d_in[2];
    float* out = (float*)d_out;

    cudaFuncSetAttribute(caps_fused_kernel,
                         cudaFuncAttributeMaxDynamicSharedMemorySize, SMEM_ALLOC);

    xsplit_kernel<<<2048, 256>>>(x);
    wsplit_kernel<<<25, 256>>>(Wt);
    caps_fused_kernel<<<1024, 512, SMEM_ALLOC>>>(b, out);
}

// round 7
// speedup vs baseline: 2.5908x; 1.0453x over previous
#include <cuda_runtime.h>
#include <cuda_fp16.h>
#include <cstdint>
#include <cstddef>

// ---------------------------------------------------------------------------
//  x: [16, 32, 32, 8, 16]  (B,H,W,I,Din) fp32
//  W: [5, 5, 16, 256]      (kh,kw,cin,co) fp32, co = o*16+d
//  b: [1, 1, 16, 16]       fp32
//  out: [16, 32, 32, 16, 16] (B,H,W,O,D) fp32
//
// Routing group p uses conv images n = 8p+q -> input capsule i = p>>1,
// b_img = 8*(p&1)+q.  CTA = (p, h, 8 w's): M=64 GEMM rows (8 q x 8 w) =
// exactly the votes its 8 routing points need.  2048 CTAs, 256 threads,
// occupancy 2 (73.7KB smem, <=128 regs).  GEMM: M=64,N=256,K=400 (k16 steps).
// fp16x2: x = x0+x1 fp16 pair, W = fp16 -> 2 MMA passes, err ~2^-12.
// 8 warps, warp tile m32n64, 4-stage cp.async, 1 sync/step.
// ---------------------------------------------------------------------------

__device__ __half g_xs[2][16 * 32 * 32 * 8 * 16];   // x split halves
__device__ __half g_ws[25 * 256 * 16];              // W as [k][n][16k], fp16

// stage: A[2 splits] 64x48B (6144) + B 256x48B (12288) = 18432 ; x4 = 73728
#define ST_BYTES   18432
#define OFF_LOGIT  66048           // after 64x258x4 dump buffer
#define OFF_ROUTE  66560
#define SMEM_ALLOC 73728

__device__ __forceinline__ uint32_t smem_u32(const void* p) {
    uint32_t a;
    asm("{ .reg .u64 t; cvta.to.shared.u64 t, %1; cvt.u32.u64 %0, t; }" : "=r"(a) : "l"(p));
    return a;
}
__device__ __forceinline__ void cp16z(uint32_t dst, const void* src, bool valid) {
    int sz = valid ? 16 : 0;
    asm volatile("cp.async.cg.shared.global [%0], [%1], 16, %2;\n"
                 :: "r"(dst), "l"(src), "r"(sz));
}
__device__ __forceinline__ void cp16(uint32_t dst, const void* src) {
    asm volatile("cp.async.cg.shared.global [%0], [%1], 16;\n" :: "r"(dst), "l"(src));
}
#define CP_COMMIT() asm volatile("cp.async.commit_group;\n")
#define CP_WAIT(n)  asm volatile("cp.async.wait_group %0;\n" :: "n"(n))

#define LDSM4(r, addr) \
    asm volatile("ldmatrix.sync.aligned.m8n8.x4.shared.b16 {%0,%1,%2,%3}, [%4];" \
                 : "=r"((r)[0]), "=r"((r)[1]), "=r"((r)[2]), "=r"((r)[3]) : "r"(addr))

#define MMA16816(c, a, bb0, bb1) \
    asm volatile("mma.sync.aligned.m16n8k16.row.col.f32.f16.f16.f32 " \
                 "{%0,%1,%2,%3}, {%4,%5,%6,%7}, {%8,%9}, {%0,%1,%2,%3};" \
                 : "+f"((c)[0]), "+f"((c)[1]), "+f"((c)[2]), "+f"((c)[3]) \
                 : "r"((a)[0]), "r"((a)[1]), "r"((a)[2]), "r"((a)[3]), \
                   "r"(bb0), "r"(bb1))

// ---------------- prep kernels ----------------
__global__ void xsplit_kernel(const float* __restrict__ x) {
    int idx = blockIdx.x * 256 + threadIdx.x;          // 4 floats per thread
    if (idx >= 16 * 32 * 32 * 8 * 16 / 4) return;
    float4 f = ((const float4*)x)[idx];
    __half h0[4], h1[4];
    float v[4] = {f.x, f.y, f.z, f.w};
#pragma unroll
    for (int j = 0; j < 4; ++j) {
        h0[j] = __float2half_rn(v[j]);
        h1[j] = __float2half_rn(v[j] - __half2float(h0[j]));
    }
    *(uint2*)&g_xs[0][idx * 4] = *(uint2*)h0;
    *(uint2*)&g_xs[1][idx * 4] = *(uint2*)h1;
}

__global__ void wsplit_kernel(const float* __restrict__ W) {
    int idx = blockIdx.x * 256 + threadIdx.x;   // k*256 + co
    if (idx >= 25 * 256) return;
    int co = idx & 255, k = idx >> 8;
#pragma unroll
    for (int cin = 0; cin < 16; ++cin)
        g_ws[idx * 16 + cin] = __float2half_rn(W[(k * 16 + cin) * 256 + co]);
}

// ---------------- main fused kernel ----------------
__device__ __forceinline__ void load_tiles(uint32_t sbase, int k, int stg_i,
                                           int h, int w0, int i_true, int b_base,
                                           int t) {
    const int kh = k / 5, kw = k - kh * 5;
    const uint32_t stg = sbase + stg_i * ST_BYTES;
    // A: 256 x 16B (1 per thread): half(2) x row(64) x split(2)
    {
        int half = t & 1, row = (t >> 1) & 63, sp = t >> 7;
        int q = row >> 3, wl = row & 7;
        int hh = h + kh - 2, ww = w0 + wl + kw - 2;
        bool valid = ((unsigned)hh < 32u) && ((unsigned)ww < 32u);
        const __half* src = valid
            ? &g_xs[sp][((((size_t)(b_base + q) * 32 + hh) * 32 + ww) * 8 + i_true) * 16 + half * 8]
            : &g_xs[0][0];
        cp16z(stg + sp * 3072 + row * 48 + half * 16, src, valid);
    }
    // B: 512 x 16B (2 per thread): half(2) x n(256)
#pragma unroll
    for (int it = 0; it < 2; ++it) {
        int j = t + it * 256;
        int half = j & 1, n = j >> 1;
        cp16(stg + 6144 + n * 48 + half * 16,
             &g_ws[((size_t)k * 256 + n) * 16 + half * 8]);
    }
}

__global__ __launch_bounds__(256, 2) void caps_fused_kernel(
    const float* __restrict__ bias, float* __restrict__ out) {
    extern __shared__ __align__(1024) char sm[];
    const uint32_t sbase = smem_u32(sm);

    const int t = threadIdx.x;
    const int wid = t >> 5, lane = t & 31;
    const int bid = blockIdx.x;
    const int wblk = bid & 3, h = (bid >> 2) & 31, p = bid >> 7;
    const int w0 = wblk * 8;
    const int i_true = p >> 1, b_base = (p & 1) * 8;

    const int wm = wid & 1;        // m block (32 rows each)
    const int wn = wid >> 1;       // n block (64 cols each)

    const uint32_t a_row  = lane & 15;
    const uint32_t a_koff = (lane >> 4) * 16;
    const uint32_t b_row  = (lane & 7) + ((lane >> 4) << 3);
    const uint32_t b_koff = ((lane >> 3) & 1) * 16;

    float acc[2][8][4];
#pragma unroll
    for (int mi = 0; mi < 2; ++mi)
#pragma unroll
        for (int ni = 0; ni < 8; ++ni)
#pragma unroll
            for (int j = 0; j < 4; ++j) acc[mi][ni][j] = 0.f;

    // prologue: stages 0,1,2
#pragma unroll
    for (int s = 0; s < 3; ++s) {
        load_tiles(sbase, s, s, h, w0, i_true, b_base, t);
        CP_COMMIT();
    }

    for (int k = 0; k < 25; ++k) {
        const int stg_i = k & 3;
        if (k <= 22) CP_WAIT(2); else if (k == 23) CP_WAIT(1); else CP_WAIT(0);
        __syncthreads();                 // stage k ready; stage (k-1)&3 free
        if (k + 3 < 25) {
            load_tiles(sbase, k + 3, (k + 3) & 3, h, w0, i_true, b_base, t);
            CP_COMMIT();
        }

        const uint32_t stg = sbase + stg_i * ST_BYTES;
        const uint32_t Ab = stg + (wm * 32 + a_row) * 48 + a_koff;
        const uint32_t Bb = stg + 6144 + (wn * 64 + b_row) * 48 + b_koff;

        uint32_t Af[2][4], Bf[4][4];
        // pass 1: x0 * w
#pragma unroll
        for (int mi = 0; mi < 2; ++mi) LDSM4(Af[mi], Ab + mi * 768);
#pragma unroll
        for (int nt = 0; nt < 4; ++nt) LDSM4(Bf[nt], Bb + nt * 768);
#pragma unroll
        for (int mi = 0; mi < 2; ++mi)
#pragma unroll
            for (int nt = 0; nt < 4; ++nt) {
                MMA16816(acc[mi][2 * nt],     Af[mi], Bf[nt][0], Bf[nt][1]);
                MMA16816(acc[mi][2 * nt + 1], Af[mi], Bf[nt][2], Bf[nt][3]);
            }
        // pass 2: x1 * w (B reused)
#pragma unroll
        for (int mi = 0; mi < 2; ++mi) LDSM4(Af[mi], Ab + 3072 + mi * 768);
#pragma unroll
        for (int mi = 0; mi < 2; ++mi)
#pragma unroll
            for (int nt = 0; nt < 4; ++nt) {
                MMA16816(acc[mi][2 * nt],     Af[mi], Bf[nt][0], Bf[nt][1]);
                MMA16816(acc[mi][2 * nt + 1], Af[mi], Bf[nt][2], Bf[nt][3]);
            }
    }
    __syncthreads();   // compute done; stage smem dead -> vote dump

    // ---- dump accumulators: Dsm[row 64][col 256], stride 258 ----
    float* Dsm = (float*)sm;
    {
        const int g = lane >> 2, tq = lane & 3;
#pragma unroll
        for (int mi = 0; mi < 2; ++mi)
#pragma unroll
            for (int ni = 0; ni < 8; ++ni) {
                int row = wm * 32 + mi * 16 + g;
                int col = wn * 64 + ni * 8 + tq * 2;
                *(float2*)&Dsm[(size_t)row * 258 + col] =
                    make_float2(acc[mi][ni][0], acc[mi][ni][1]);
                *(float2*)&Dsm[(size_t)(row + 8) * 258 + col] =
                    make_float2(acc[mi][ni][2], acc[mi][ni][3]);
            }
    }
    __syncthreads();

    // ---- fused routing: 8 points, 1 per step (256 threads = (o,d)) ----
    float* lg = (float*)(sm + OFF_LOGIT);   // [q*16+o] 128
    float* rt = (float*)(sm + OFF_ROUTE);
    const float bval = bias[t];
    const int o = t >> 4, d = t & 15;

    for (int pt = 0; pt < 8; ++pt) {
        float vq[8];
#pragma unroll
        for (int q = 0; q < 8; ++q)
            vq[q] = Dsm[(size_t)(q * 8 + pt) * 258 + t];

        // iter 0: softmax(0) = 1/16
        float pre = bval;
#pragma unroll
        for (int q = 0; q < 8; ++q) pre = fmaf(0.0625f, vq[q], pre);
        float sq = pre * pre;
#pragma unroll
        for (int st = 8; st; st >>= 1)
            sq += __shfl_xor_sync(0xffffffffu, sq, st, 16);
        float act = pre * sqrtf(sq) / (1.f + sq);

        {   // agreement -> logits (initial logits 0, plain store)
            float r[8];
#pragma unroll
            for (int q = 0; q < 8; ++q) r[q] = vq[q] * act;
#pragma unroll
            for (int st = 8; st; st >>= 1)
#pragma unroll
                for (int q = 0; q < 8; ++q)
                    r[q] += __shfl_xor_sync(0xffffffffu, r[q], st, 16);
            if (d < 8) {
                float val = r[0];
#pragma unroll
                for (int q = 1; q < 8; ++q) if (d == q) val = r[q];
                lg[d * 16 + o] = val;
            }
        }
        __syncthreads();

#pragma unroll
        for (int it = 1; it < 3; ++it) {
            if (t < 128) {          // softmax over o, per input capsule
                float l = lg[t];
                float mx = l;
#pragma unroll
                for (int st = 8; st; st >>= 1)
                    mx = fmaxf(mx, __shfl_xor_sync(0xffffffffu, mx, st, 16));
                float e = __expf(l - mx);
                float sum = e;
#pragma unroll
                for (int st = 8; st; st >>= 1)
                    sum += __shfl_xor_sync(0xffffffffu, sum, st, 16);
                rt[t] = e / sum;
            }
            __syncthreads();

            pre = bval;
#pragma unroll
            for (int q = 0; q < 8; ++q)
                pre = fmaf(rt[q * 16 + o], vq[q], pre);
            sq = pre * pre;
#pragma unroll
            for (int st = 8; st; st >>= 1)
                sq += __shfl_xor_sync(0xffffffffu, sq, st, 16);
            act = pre * sqrtf(sq) / (1.f + sq);

            if (it == 1) {
                float r[8];
#pragma unroll
                for (int q = 0; q < 8; ++q) r[q] = vq[q] * act;
#pragma unroll
                for (int st = 8; st; st >>= 1)
#pragma unroll
                    for (int q = 0; q < 8; ++q)
                        r[q] += __shfl_xor_sync(0xffffffffu, r[q], st, 16);
                if (d < 8) {
                    float val = r[0];
#pragma unroll
                    for (int q = 1; q < 8; ++q) if (d == q) val = r[q];
                    lg[d * 16 + o] += val;
                }
                __syncthreads();
            }
        }

        out[(((size_t)p * 32 + h) * 32 + (w0 + pt)) * 256 + t] = act;
        __syncthreads();
    }
}

extern "C" void kernel_launch(void* const* d_in, const int* in_sizes, int n_in,
                              void* d_out, int out_size) {
    const float* x  = (const float*)d_in[0];
    const float* Wt = (const float*)d_in[1];
    const float* b  = (const float*)d_in[2];
    float* out = (float*)d_out;

    cudaFuncSetAttribute(caps_fused_kernel,
                         cudaFuncAttributeMaxDynamicSharedMemorySize, SMEM_ALLOC);

    xsplit_kernel<<<2048, 256>>>(x);
    wsplit_kernel<<<25, 256>>>(Wt);
    caps_fused_kernel<<<2048, 256, SMEM_ALLOC>>>(b, out);
}